// round 1
// baseline (speedup 1.0000x reference)
#include <cuda_runtime.h>
#include <math.h>

#define N_NODES 4096
#define FIN     256
#define NHEAD   4
#define FHID    64
#define FFIN    64
#define NPROJ   16
#define MAXD    128   // max neighbors per row (Binomial(4096,0.005): mean ~21, max ~45)

// ---------------- scratch (device globals; no allocation allowed) ----------------
__device__ int   g_cols[2][N_NODES][MAXD];
__device__ int   g_deg [2][N_NODES];
__device__ float g_Bcat[FIN][512];          // concatenated layer-1 weights, both gats
__device__ float g_Wh  [N_NODES][512];      // x @ Wcat   (cols: g*256 + h*64 + f)
__device__ float g_s1  [2][NHEAD][N_NODES];
__device__ float g_s2  [2][NHEAD][N_NODES];
__device__ float g_hcat[2][N_NODES][256];   // layer-1 outputs (head-concat)
__device__ float g_Wh2 [2][N_NODES][64];    // hcat @ Wo
__device__ float g_s1o [2][N_NODES];
__device__ float g_s2o [2][N_NODES];
__device__ float g_emb [2][N_NODES][64];

// ---------------- kernel 1: dense mask -> CSR (one warp per row) ----------------
__global__ void build_csr(const float* __restrict__ m0, const float* __restrict__ m1) {
    int w    = blockIdx.x * 8 + (threadIdx.x >> 5);   // 8192 warps
    int lane = threadIdx.x & 31;
    int g = w >> 12;
    int r = w & 4095;
    const float* mask = g ? m1 : m0;
    size_t base = (size_t)r * N_NODES;
    unsigned lt = (1u << lane) - 1u;
    int cnt = 0;
    for (int jb = 0; jb < N_NODES; jb += 32) {
        float v = mask[base + jb + lane];
        unsigned b = __ballot_sync(0xffffffffu, v > 0.f);
        if (v > 0.f) {
            int pos = cnt + __popc(b & lt);
            if (pos < MAXD) g_cols[g][r][pos] = jb + lane;
        }
        cnt += __popc(b);
    }
    if (lane == 0) g_deg[g][r] = cnt < MAXD ? cnt : MAXD;
}

// ---------------- kernel 2: pack W1/W2 into one [256,512] B matrix ----------------
__global__ void fill_bcat(const float* __restrict__ W1, const float* __restrict__ W2) {
    int idx = blockIdx.x * 256 + threadIdx.x;  // 131072
    int k = idx >> 9, c = idx & 511;
    float v;
    if (c < 256) v = W1[((c >> 6) * FIN + k) * FHID + (c & 63)];
    else { int cc = c - 256; v = W2[((cc >> 6) * FIN + k) * FHID + (cc & 63)]; }
    g_Bcat[k][c] = v;
}

// ---------------- kernel 3: tiled fp32 GEMM  C[M,N] = A[M,K] @ B[K,N] -------------
// BM=128, BN=64, BK=16, 256 threads, 8x4 micro-tile per thread.
__global__ void gemm_kernel(const float* __restrict__ A, int lda,
                            const float* __restrict__ B, int ldb,
                            float* __restrict__ C, int ldc, int K) {
    const int BM = 128, BN = 64, BK = 16;
    __shared__ float As[BK][BM + 4];
    __shared__ float Bs[BK][BN];
    int tid = threadIdx.x;
    int tx = tid & 15, ty = tid >> 4;
    int m0 = blockIdx.x * BM, n0 = blockIdx.y * BN;
    float acc[8][4] = {};
    for (int kb = 0; kb < K; kb += BK) {
        #pragma unroll
        for (int i = 0; i < 8; i++) {           // 2048 A elems
            int e = i * 256 + tid;
            int m = e >> 4, k = e & 15;
            As[k][m] = A[(size_t)(m0 + m) * lda + kb + k];
        }
        #pragma unroll
        for (int i = 0; i < 4; i++) {           // 1024 B elems
            int e = i * 256 + tid;
            int k = e >> 6, n = e & 63;
            Bs[k][n] = B[(size_t)(kb + k) * ldb + n0 + n];
        }
        __syncthreads();
        #pragma unroll
        for (int kk = 0; kk < BK; kk++) {
            float a[8], b[4];
            #pragma unroll
            for (int r = 0; r < 8; r++) a[r] = As[kk][ty * 8 + r];
            #pragma unroll
            for (int c = 0; c < 4; c++) b[c] = Bs[kk][tx * 4 + c];
            #pragma unroll
            for (int r = 0; r < 8; r++)
                #pragma unroll
                for (int c = 0; c < 4; c++)
                    acc[r][c] += a[r] * b[c];
        }
        __syncthreads();
    }
    #pragma unroll
    for (int r = 0; r < 8; r++)
        #pragma unroll
        for (int c = 0; c < 4; c++)
            C[(size_t)(m0 + ty * 8 + r) * ldc + n0 + tx * 4 + c] = acc[r][c];
}

// ---------------- kernel 4: layer-1 attention logits s1/s2 (warp per (i,g,h)) -----
__global__ void s_layer1(const float* __restrict__ a1, const float* __restrict__ a2) {
    int i = blockIdx.x;
    int wid = threadIdx.x >> 5, lane = threadIdx.x & 31;
    int g = wid >> 2, h = wid & 3;
    const float* a = (g ? a2 : a1) + h * 128;   // [128] = [a_src(64) | a_dst(64)]
    int base = g * 256 + h * 64;
    float w0 = g_Wh[i][base + lane];
    float w1 = g_Wh[i][base + 32 + lane];
    float s1 = w0 * a[lane]      + w1 * a[32 + lane];
    float s2 = w0 * a[64 + lane] + w1 * a[96 + lane];
    #pragma unroll
    for (int off = 16; off; off >>= 1) {
        s1 += __shfl_xor_sync(0xffffffffu, s1, off);
        s2 += __shfl_xor_sync(0xffffffffu, s2, off);
    }
    if (lane == 0) { g_s1[g][h][i] = s1; g_s2[g][h][i] = s2; }
}

// ---------------- kernel 5: layer-1 sparse softmax + SpMM + ELU -------------------
__global__ void attn_layer1() {
    int i = blockIdx.x, g = blockIdx.y;
    int tid = threadIdx.x;  // 256
    __shared__ int   sh_cols[MAXD];
    __shared__ float sh_e[4][MAXD];
    __shared__ float sh_sum[4];
    int d = g_deg[g][i];
    if (tid < d) sh_cols[tid] = g_cols[g][i][tid];
    __syncthreads();
    int wid = tid >> 5, lane = tid & 31;
    if (wid < 4) {
        int h = wid;
        float s1v = g_s1[g][h][i];
        float m = -INFINITY;
        for (int k = lane; k < d; k += 32) {
            float z = s1v + g_s2[g][h][sh_cols[k]];
            z = z >= 0.f ? z : 0.2f * z;            // leaky relu
            sh_e[h][k] = z;
            m = fmaxf(m, z);
        }
        #pragma unroll
        for (int off = 16; off; off >>= 1) m = fmaxf(m, __shfl_xor_sync(0xffffffffu, m, off));
        float sum = 0.f;
        for (int k = lane; k < d; k += 32) {
            float p = __expf(sh_e[h][k] - m);
            sh_e[h][k] = p;
            sum += p;
        }
        #pragma unroll
        for (int off = 16; off; off >>= 1) sum += __shfl_xor_sync(0xffffffffu, sum, off);
        if (lane == 0) sh_sum[h] = sum;
    }
    __syncthreads();
    int h = tid >> 6;
    float acc = 0.f;
    for (int k = 0; k < d; k++)
        acc += sh_e[h][k] * g_Wh[sh_cols[k]][g * 256 + tid];
    acc /= sh_sum[h];
    g_hcat[g][i][tid] = acc > 0.f ? acc : expm1f(acc);   // elu
}

// ---------------- kernel 6: layer-2 attention logits (warp per (i,g)) -------------
__global__ void s_layer2(const float* __restrict__ ao1, const float* __restrict__ ao2) {
    int i = blockIdx.x;
    int g = threadIdx.x >> 5, lane = threadIdx.x & 31;
    const float* ao = g ? ao2 : ao1;
    float w0 = g_Wh2[g][i][lane], w1 = g_Wh2[g][i][32 + lane];
    float s1 = w0 * ao[lane]      + w1 * ao[32 + lane];
    float s2 = w0 * ao[64 + lane] + w1 * ao[96 + lane];
    #pragma unroll
    for (int off = 16; off; off >>= 1) {
        s1 += __shfl_xor_sync(0xffffffffu, s1, off);
        s2 += __shfl_xor_sync(0xffffffffu, s2, off);
    }
    if (lane == 0) { g_s1o[g][i] = s1; g_s2o[g][i] = s2; }
}

// ---------------- kernel 7: layer-2 sparse softmax + SpMM + ELU -------------------
__global__ void attn_layer2() {
    int i = blockIdx.x, g = blockIdx.y;
    int tid = threadIdx.x;  // 64
    __shared__ int   sh_cols[MAXD];
    __shared__ float sh_e[MAXD];
    __shared__ float sh_sum;
    int d = g_deg[g][i];
    for (int k = tid; k < d; k += 64) sh_cols[k] = g_cols[g][i][k];
    __syncthreads();
    if (tid < 32) {
        float s1v = g_s1o[g][i];
        float m = -INFINITY;
        for (int k = tid; k < d; k += 32) {
            float z = s1v + g_s2o[g][sh_cols[k]];
            z = z >= 0.f ? z : 0.2f * z;
            sh_e[k] = z;
            m = fmaxf(m, z);
        }
        #pragma unroll
        for (int off = 16; off; off >>= 1) m = fmaxf(m, __shfl_xor_sync(0xffffffffu, m, off));
        float sum = 0.f;
        for (int k = tid; k < d; k += 32) {
            float p = __expf(sh_e[k] - m);
            sh_e[k] = p;
            sum += p;
        }
        #pragma unroll
        for (int off = 16; off; off >>= 1) sum += __shfl_xor_sync(0xffffffffu, sum, off);
        if (tid == 0) sh_sum = sum;
    }
    __syncthreads();
    float acc = 0.f;
    for (int k = 0; k < d; k++)
        acc += sh_e[k] * g_Wh2[g][sh_cols[k]][tid];
    acc /= sh_sum;
    g_emb[g][i][tid] = acc > 0.f ? acc : expm1f(acc);    // elu (applied once, per reference)
}

// ---------------- kernel 8: semantic attention fusion -----------------------------
__global__ void final_kernel(const float* __restrict__ Wp1, const float* __restrict__ bp1,
                             const float* __restrict__ Wp2, float* __restrict__ out) {
    int i = blockIdx.x, tid = threadIdx.x;  // 64
    __shared__ float se[2][64];
    __shared__ float tt[2][16];
    __shared__ float beta[2];
    se[0][tid] = g_emb[0][i][tid];
    se[1][tid] = g_emb[1][i][tid];
    __syncthreads();
    if (tid < 32) {
        int g = tid >> 4, p = tid & 15;
        float s = bp1[p];
        for (int f = 0; f < 64; f++) s += se[g][f] * Wp1[f * NPROJ + p];
        tt[g][p] = tanhf(s);
    }
    __syncthreads();
    if (tid == 0) {
        float w0 = 0.f, w1 = 0.f;
        #pragma unroll
        for (int p = 0; p < NPROJ; p++) { w0 += tt[0][p] * Wp2[p]; w1 += tt[1][p] * Wp2[p]; }
        float m = fmaxf(w0, w1);
        float b0 = __expf(w0 - m), b1 = __expf(w1 - m);
        float s = b0 + b1;
        beta[0] = b0 / s; beta[1] = b1 / s;
    }
    __syncthreads();
    out[(size_t)i * 64 + tid] = beta[0] * se[0][tid] + beta[1] * se[1][tid];
}

// ---------------- launch ----------------------------------------------------------
extern "C" void kernel_launch(void* const* d_in, const int* in_sizes, int n_in,
                              void* d_out, int out_size) {
    const float* x    = (const float*)d_in[0];
    const float* sadj = (const float*)d_in[1];
    const float* sadj2= (const float*)d_in[2];
    const float* W1   = (const float*)d_in[3];
    const float* a1   = (const float*)d_in[4];
    const float* Wo1  = (const float*)d_in[5];
    const float* ao1  = (const float*)d_in[6];
    const float* W2   = (const float*)d_in[7];
    const float* a2   = (const float*)d_in[8];
    const float* Wo2  = (const float*)d_in[9];
    const float* ao2  = (const float*)d_in[10];
    const float* Wp1  = (const float*)d_in[11];
    const float* bp1  = (const float*)d_in[12];
    const float* Wp2  = (const float*)d_in[13];
    float* out = (float*)d_out;

    float *pBcat, *pWh, *pHcat, *pWh2;
    cudaGetSymbolAddress((void**)&pBcat, g_Bcat);
    cudaGetSymbolAddress((void**)&pWh,   g_Wh);
    cudaGetSymbolAddress((void**)&pHcat, g_hcat);
    cudaGetSymbolAddress((void**)&pWh2,  g_Wh2);

    // 1. sparsify both masks
    build_csr<<<1024, 256>>>(sadj, sadj2);
    // 2. pack layer-1 weights
    fill_bcat<<<512, 256>>>(W1, W2);
    // 3. Wh = x @ Wcat   [4096,256]@[256,512]
    gemm_kernel<<<dim3(32, 8), 256>>>(x, FIN, pBcat, 512, pWh, 512, FIN);
    // 4. layer-1 attention logits
    s_layer1<<<N_NODES, 256>>>(a1, a2);
    // 5. layer-1 sparse attention + elu
    attn_layer1<<<dim3(N_NODES, 2), 256>>>();
    // 6. Wh2_g = hcat_g @ Wo_g   [4096,256]@[256,64], per graph
    gemm_kernel<<<dim3(32, 1), 256>>>(pHcat,                       256, Wo1, 64, pWh2,                     64, 256);
    gemm_kernel<<<dim3(32, 1), 256>>>(pHcat + (size_t)N_NODES*256, 256, Wo2, 64, pWh2 + (size_t)N_NODES*64, 64, 256);
    // 7. layer-2 attention logits
    s_layer2<<<N_NODES, 64>>>(ao1, ao2);
    // 8. layer-2 sparse attention + elu
    attn_layer2<<<dim3(N_NODES, 2), 64>>>();
    // 9. semantic attention fusion
    final_kernel<<<N_NODES, 64>>>(Wp1, bp1, Wp2, out);
}

// round 2
// speedup vs baseline: 1.2049x; 1.2049x over previous
#include <cuda_runtime.h>
#include <math.h>

#define N_NODES 4096
#define FIN     256
#define NHEAD   4
#define FHID    64
#define FFIN    64
#define NPROJ   16
#define MAXD    128

// ---------------- scratch ----------------
__device__ int   g_cols[2][N_NODES][MAXD];
__device__ int   g_deg [2][N_NODES];
__device__ float g_Wh  [N_NODES][512];      // x @ Wcat   (cols: g*256 + h*64 + f)
__device__ float g_s1  [2][NHEAD][N_NODES];
__device__ float g_s2  [2][NHEAD][N_NODES];
__device__ float g_hcat[2][N_NODES][256];   // layer-1 outputs (head-concat)
__device__ float g_Wh2 [2][N_NODES][64];
__device__ float g_s1o [2][N_NODES];
__device__ float g_s2o [2][N_NODES];

// =====================================================================
// Phase 1 (heterogeneous): blocks [0,256) do GEMM1 + logit epilogue,
// blocks [256,1280) do dense-mask -> CSR (DRAM-bound, runs concurrently).
// =====================================================================
__global__ void phase1(const float* __restrict__ x,
                       const float* __restrict__ W1, const float* __restrict__ W2,
                       const float* __restrict__ a1, const float* __restrict__ a2,
                       const float* __restrict__ m0, const float* __restrict__ m1) {
    int bid = blockIdx.x;
    int tid = threadIdx.x;

    if (bid >= 256) {
        // ---------------- CSR build: one warp per row, float4 scan ----------------
        int w    = (bid - 256) * 8 + (tid >> 5);
        int lane = tid & 31;
        int g = w >> 12, r = w & 4095;
        const float4* mask = (const float4*)((g ? m1 : m0) + (size_t)r * N_NODES);
        int cnt = 0;
        for (int jb = 0; jb < 1024; jb += 32) {
            float4 v = mask[jb + lane];
            unsigned nib = (v.x > 0.f) | ((v.y > 0.f) << 1) | ((v.z > 0.f) << 2) | ((v.w > 0.f) << 3);
            int c4 = __popc(nib);
            int s = c4;
            #pragma unroll
            for (int off = 1; off < 32; off <<= 1) {
                int t = __shfl_up_sync(0xffffffffu, s, off);
                if (lane >= off) s += t;
            }
            int base = cnt + s - c4;
            int colbase = (jb + lane) * 4;
            int p = 0;
            if (nib & 1) { if (base + p < MAXD) g_cols[g][r][base + p] = colbase;     p++; }
            if (nib & 2) { if (base + p < MAXD) g_cols[g][r][base + p] = colbase + 1; p++; }
            if (nib & 4) { if (base + p < MAXD) g_cols[g][r][base + p] = colbase + 2; p++; }
            if (nib & 8) { if (base + p < MAXD) g_cols[g][r][base + p] = colbase + 3; }
            cnt += __shfl_sync(0xffffffffu, s, 31);
        }
        if (lane == 0) g_deg[g][r] = cnt < MAXD ? cnt : MAXD;
        return;
    }

    // ---------------- GEMM1: Wh = x @ Wcat, tile 128x64, + s1/s2 epilogue ----------
    __shared__ float As[16][132];
    __shared__ float Bs[16][64];
    int bx = bid & 31, by = bid >> 5;         // by in [0,8)
    int m0r = bx * 128, n0 = by * 64;
    int gsel = by >> 2, h = by & 3;
    const float* W  = gsel ? W2 : W1;         // [4,256,64]
    const float* av = (gsel ? a2 : a1) + h * 128;
    int tx = tid & 15, ty = tid >> 4;

    float acc[8][4] = {};
    for (int kb = 0; kb < FIN; kb += 16) {
        #pragma unroll
        for (int i = 0; i < 2; i++) {
            int e4 = i * 256 + tid;
            int m = e4 >> 2, k4 = e4 & 3;
            float4 v = *(const float4*)(x + (size_t)(m0r + m) * FIN + kb + k4 * 4);
            As[k4 * 4 + 0][m] = v.x; As[k4 * 4 + 1][m] = v.y;
            As[k4 * 4 + 2][m] = v.z; As[k4 * 4 + 3][m] = v.w;
        }
        {
            int k = tid >> 4, nf = (tid & 15) * 4;
            float4 bv = *(const float4*)(W + ((size_t)(h * FIN + kb + k)) * FHID + nf);
            *(float4*)&Bs[k][nf] = bv;
        }
        __syncthreads();
        #pragma unroll
        for (int kk = 0; kk < 16; kk++) {
            float a[8], b[4];
            #pragma unroll
            for (int r = 0; r < 8; r++) a[r] = As[kk][ty * 8 + r];
            #pragma unroll
            for (int c = 0; c < 4; c++) b[c] = Bs[kk][tx * 4 + c];
            #pragma unroll
            for (int r = 0; r < 8; r++)
                #pragma unroll
                for (int c = 0; c < 4; c++)
                    acc[r][c] += a[r] * b[c];
        }
        __syncthreads();
    }
    // write C (float4)
    #pragma unroll
    for (int r = 0; r < 8; r++) {
        int m = m0r + ty * 8 + r;
        float4 v = make_float4(acc[r][0], acc[r][1], acc[r][2], acc[r][3]);
        *(float4*)&g_Wh[m][n0 + tx * 4] = v;
    }
    // epilogue: s1[m] = Wh_row . a_src,  s2[m] = Wh_row . a_dst  (cols all in-tile)
    float a_s[4], a_d[4];
    #pragma unroll
    for (int c = 0; c < 4; c++) {
        a_s[c] = __ldg(av + tx * 4 + c);
        a_d[c] = __ldg(av + 64 + tx * 4 + c);
    }
    #pragma unroll
    for (int r = 0; r < 8; r++) {
        float s1 = 0.f, s2 = 0.f;
        #pragma unroll
        for (int c = 0; c < 4; c++) { s1 += acc[r][c] * a_s[c]; s2 += acc[r][c] * a_d[c]; }
        #pragma unroll
        for (int off = 1; off < 16; off <<= 1) {
            s1 += __shfl_xor_sync(0xffffffffu, s1, off);
            s2 += __shfl_xor_sync(0xffffffffu, s2, off);
        }
        if (tx == 0) {
            int m = m0r + ty * 8 + r;
            g_s1[gsel][h][m] = s1;
            g_s2[gsel][h][m] = s2;
        }
    }
}

// =====================================================================
// Layer-1 sparse softmax + SpMM + ELU  (block = one (node, graph))
// =====================================================================
__global__ void attn_layer1() {
    int i = blockIdx.x, g = blockIdx.y;
    int tid = threadIdx.x;  // 256
    __shared__ int   sh_cols[MAXD];
    __shared__ float sh_e[4][MAXD];
    __shared__ float sh_sum[4];
    int d = g_deg[g][i];
    if (tid < d) sh_cols[tid] = g_cols[g][i][tid];
    __syncthreads();
    int wid = tid >> 5, lane = tid & 31;
    if (wid < 4) {
        int h = wid;
        float s1v = g_s1[g][h][i];
        float m = -INFINITY;
        for (int k = lane; k < d; k += 32) {
            float z = s1v + g_s2[g][h][sh_cols[k]];
            z = z >= 0.f ? z : 0.2f * z;
            sh_e[h][k] = z;
            m = fmaxf(m, z);
        }
        #pragma unroll
        for (int off = 16; off; off >>= 1) m = fmaxf(m, __shfl_xor_sync(0xffffffffu, m, off));
        float sum = 0.f;
        for (int k = lane; k < d; k += 32) {
            float p = __expf(sh_e[h][k] - m);
            sh_e[h][k] = p;
            sum += p;
        }
        #pragma unroll
        for (int off = 16; off; off >>= 1) sum += __shfl_xor_sync(0xffffffffu, sum, off);
        if (lane == 0) sh_sum[h] = sum;
    }
    __syncthreads();
    int h = tid >> 6;
    int colbase = g * 256 + tid;
    float acc = 0.f;
    int k = 0;
    for (; k + 4 <= d; k += 4) {
        int c0 = sh_cols[k], c1 = sh_cols[k+1], c2 = sh_cols[k+2], c3 = sh_cols[k+3];
        float e0 = sh_e[h][k], e1 = sh_e[h][k+1], e2 = sh_e[h][k+2], e3 = sh_e[h][k+3];
        acc += e0 * g_Wh[c0][colbase] + e1 * g_Wh[c1][colbase]
             + e2 * g_Wh[c2][colbase] + e3 * g_Wh[c3][colbase];
    }
    for (; k < d; k++) acc += sh_e[h][k] * g_Wh[sh_cols[k]][colbase];
    acc /= sh_sum[h];
    g_hcat[g][i][tid] = acc > 0.f ? acc : expm1f(acc);
}

// =====================================================================
// GEMM2 (both graphs, one launch): Wh2_g = hcat_g @ Wo_g, tile 64x64,
// + s1o/s2o epilogue.  grid (64, 2), block 256, microtile 4x4.
// =====================================================================
__global__ void gemm2f(const float* __restrict__ Wo1, const float* __restrict__ Wo2,
                       const float* __restrict__ ao1, const float* __restrict__ ao2) {
    __shared__ float As[16][68];
    __shared__ float Bs[16][64];
    int g = blockIdx.y;
    int m0r = blockIdx.x * 64;
    const float* A  = &g_hcat[g][0][0];
    const float* B  = g ? Wo2 : Wo1;
    const float* ao = g ? ao2 : ao1;
    int tid = threadIdx.x;
    int tx = tid & 15, ty = tid >> 4;

    float acc[4][4] = {};
    for (int kb = 0; kb < 256; kb += 16) {
        {   // A tile 64x16 = 256 float4
            int m = tid >> 2, k4 = tid & 3;
            float4 v = *(const float4*)(A + (size_t)(m0r + m) * 256 + kb + k4 * 4);
            As[k4 * 4 + 0][m] = v.x; As[k4 * 4 + 1][m] = v.y;
            As[k4 * 4 + 2][m] = v.z; As[k4 * 4 + 3][m] = v.w;
        }
        {
            int k = tid >> 4, nf = (tid & 15) * 4;
            float4 bv = *(const float4*)(B + (size_t)(kb + k) * 64 + nf);
            *(float4*)&Bs[k][nf] = bv;
        }
        __syncthreads();
        #pragma unroll
        for (int kk = 0; kk < 16; kk++) {
            float a[4], b[4];
            #pragma unroll
            for (int r = 0; r < 4; r++) a[r] = As[kk][ty * 4 + r];
            #pragma unroll
            for (int c = 0; c < 4; c++) b[c] = Bs[kk][tx * 4 + c];
            #pragma unroll
            for (int r = 0; r < 4; r++)
                #pragma unroll
                for (int c = 0; c < 4; c++)
                    acc[r][c] += a[r] * b[c];
        }
        __syncthreads();
    }
    #pragma unroll
    for (int r = 0; r < 4; r++) {
        int m = m0r + ty * 4 + r;
        float4 v = make_float4(acc[r][0], acc[r][1], acc[r][2], acc[r][3]);
        *(float4*)&g_Wh2[g][m][tx * 4] = v;
    }
    float a_s[4], a_d[4];
    #pragma unroll
    for (int c = 0; c < 4; c++) {
        a_s[c] = __ldg(ao + tx * 4 + c);
        a_d[c] = __ldg(ao + 64 + tx * 4 + c);
    }
    #pragma unroll
    for (int r = 0; r < 4; r++) {
        float s1 = 0.f, s2 = 0.f;
        #pragma unroll
        for (int c = 0; c < 4; c++) { s1 += acc[r][c] * a_s[c]; s2 += acc[r][c] * a_d[c]; }
        #pragma unroll
        for (int off = 1; off < 16; off <<= 1) {
            s1 += __shfl_xor_sync(0xffffffffu, s1, off);
            s2 += __shfl_xor_sync(0xffffffffu, s2, off);
        }
        if (tx == 0) {
            int m = m0r + ty * 4 + r;
            g_s1o[g][m] = s1;
            g_s2o[g][m] = s2;
        }
    }
}

// =====================================================================
// Layer-2 sparse attention (both graphs) + ELU + semantic fusion.
// block = one node, 128 threads (tid<64 -> graph 0, else graph 1).
// =====================================================================
__global__ void attn2_final(const float* __restrict__ Wp1, const float* __restrict__ bp1,
                            const float* __restrict__ Wp2, float* __restrict__ out) {
    int i = blockIdx.x, tid = threadIdx.x;  // 128
    __shared__ int   cols[2][MAXD];
    __shared__ float ev[2][MAXD];
    __shared__ float ssum[2];
    __shared__ float se[2][64];
    __shared__ float tt[2][16];
    __shared__ float beta[2];
    int gg = tid >> 6, tf = tid & 63;
    int dgg = g_deg[gg][i];
    for (int k = tf; k < dgg; k += 64) cols[gg][k] = g_cols[gg][i][k];
    __syncthreads();
    int w = tid >> 5, lane = tid & 31;
    if ((w & 1) == 0) {   // warps 0, 2 run softmax for g = 0, 1
        int g = w >> 1;
        int d = g_deg[g][i];
        float s1v = g_s1o[g][i];
        float m = -INFINITY;
        for (int k = lane; k < d; k += 32) {
            float z = s1v + g_s2o[g][cols[g][k]];
            z = z >= 0.f ? z : 0.2f * z;
            ev[g][k] = z;
            m = fmaxf(m, z);
        }
        #pragma unroll
        for (int off = 16; off; off >>= 1) m = fmaxf(m, __shfl_xor_sync(0xffffffffu, m, off));
        float sum = 0.f;
        for (int k = lane; k < d; k += 32) {
            float p = __expf(ev[g][k] - m);
            ev[g][k] = p;
            sum += p;
        }
        #pragma unroll
        for (int off = 16; off; off >>= 1) sum += __shfl_xor_sync(0xffffffffu, sum, off);
        if (lane == 0) ssum[g] = sum;
    }
    __syncthreads();
    float acc = 0.f;
    int k = 0;
    for (; k + 4 <= dgg; k += 4) {
        int c0 = cols[gg][k], c1 = cols[gg][k+1], c2 = cols[gg][k+2], c3 = cols[gg][k+3];
        float e0 = ev[gg][k], e1 = ev[gg][k+1], e2 = ev[gg][k+2], e3 = ev[gg][k+3];
        acc += e0 * g_Wh2[gg][c0][tf] + e1 * g_Wh2[gg][c1][tf]
             + e2 * g_Wh2[gg][c2][tf] + e3 * g_Wh2[gg][c3][tf];
    }
    for (; k < dgg; k++) acc += ev[gg][k] * g_Wh2[gg][cols[gg][k]][tf];
    float v = acc / ssum[gg];
    se[gg][tf] = v > 0.f ? v : expm1f(v);
    __syncthreads();
    if (tid < 32) {
        int g = tid >> 4, p = tid & 15;
        float s = bp1[p];
        #pragma unroll
        for (int f = 0; f < 64; f++) s += se[g][f] * Wp1[f * NPROJ + p];
        tt[g][p] = tanhf(s);
    }
    __syncthreads();
    if (tid == 0) {
        float w0 = 0.f, w1 = 0.f;
        #pragma unroll
        for (int p = 0; p < NPROJ; p++) { w0 += tt[0][p] * Wp2[p]; w1 += tt[1][p] * Wp2[p]; }
        float m = fmaxf(w0, w1);
        float b0 = __expf(w0 - m), b1 = __expf(w1 - m);
        float s = b0 + b1;
        beta[0] = b0 / s; beta[1] = b1 / s;
    }
    __syncthreads();
    if (tid < 64)
        out[(size_t)i * 64 + tid] = beta[0] * se[0][tid] + beta[1] * se[1][tid];
}

// ---------------- launch ----------------
extern "C" void kernel_launch(void* const* d_in, const int* in_sizes, int n_in,
                              void* d_out, int out_size) {
    const float* x    = (const float*)d_in[0];
    const float* sadj = (const float*)d_in[1];
    const float* sadj2= (const float*)d_in[2];
    const float* W1   = (const float*)d_in[3];
    const float* a1   = (const float*)d_in[4];
    const float* Wo1  = (const float*)d_in[5];
    const float* ao1  = (const float*)d_in[6];
    const float* W2   = (const float*)d_in[7];
    const float* a2   = (const float*)d_in[8];
    const float* Wo2  = (const float*)d_in[9];
    const float* ao2  = (const float*)d_in[10];
    const float* Wp1  = (const float*)d_in[11];
    const float* bp1  = (const float*)d_in[12];
    const float* Wp2  = (const float*)d_in[13];
    float* out = (float*)d_out;

    phase1<<<1280, 256>>>(x, W1, W2, a1, a2, sadj, sadj2);
    attn_layer1<<<dim3(N_NODES, 2), 256>>>();
    gemm2f<<<dim3(64, 2), 256>>>(Wo1, Wo2, ao1, ao2);
    attn2_final<<<N_NODES, 128>>>(Wp1, bp1, Wp2, out);
}

// round 4
// speedup vs baseline: 1.2854x; 1.0668x over previous
#include <cuda_runtime.h>
#include <math.h>

#define N_NODES 4096
#define FIN     256
#define NHEAD   4
#define FHID    64
#define FFIN    64
#define NPROJ   16
#define MAXD    128

// ---------------- scratch ----------------
__device__ int   g_cols[2][N_NODES][MAXD];
__device__ int   g_deg [2][N_NODES];
__device__ float g_Wh  [N_NODES][512];      // x @ Wcat   (cols: g*256 + h*64 + f)
__device__ float g_s1  [2][NHEAD][N_NODES];
__device__ float g_s2  [2][NHEAD][N_NODES];
__device__ float g_hcat[2][N_NODES][256];   // layer-1 outputs (head-concat)
__device__ float g_Wh2 [2][N_NODES][64];
__device__ float g_s1o [2][N_NODES];
__device__ float g_s2o [2][N_NODES];

// =====================================================================
// Phase 1 (heterogeneous): blocks [0,256) do GEMM1 + logit epilogue,
// blocks [256,1280) do dense-mask -> CSR (DRAM-bound, runs concurrently).
// =====================================================================
__global__ void phase1(const float* __restrict__ x,
                       const float* __restrict__ W1, const float* __restrict__ W2,
                       const float* __restrict__ a1, const float* __restrict__ a2,
                       const float* __restrict__ m0, const float* __restrict__ m1) {
    int bid = blockIdx.x;
    int tid = threadIdx.x;

    if (bid >= 256) {
        // ---------------- CSR build: one warp per row, float4 scan ----------------
        int w    = (bid - 256) * 8 + (tid >> 5);
        int lane = tid & 31;
        int g = w >> 12, r = w & 4095;
        const float4* mask = (const float4*)((g ? m1 : m0) + (size_t)r * N_NODES);
        int cnt = 0;
        for (int jb = 0; jb < 1024; jb += 32) {
            float4 v = mask[jb + lane];
            unsigned nib = (v.x > 0.f) | ((v.y > 0.f) << 1) | ((v.z > 0.f) << 2) | ((v.w > 0.f) << 3);
            int c4 = __popc(nib);
            int s = c4;
            #pragma unroll
            for (int off = 1; off < 32; off <<= 1) {
                int t = __shfl_up_sync(0xffffffffu, s, off);
                if (lane >= off) s += t;
            }
            int base = cnt + s - c4;
            int colbase = (jb + lane) * 4;
            int p = 0;
            if (nib & 1) { if (base + p < MAXD) g_cols[g][r][base + p] = colbase;     p++; }
            if (nib & 2) { if (base + p < MAXD) g_cols[g][r][base + p] = colbase + 1; p++; }
            if (nib & 4) { if (base + p < MAXD) g_cols[g][r][base + p] = colbase + 2; p++; }
            if (nib & 8) { if (base + p < MAXD) g_cols[g][r][base + p] = colbase + 3; }
            cnt += __shfl_sync(0xffffffffu, s, 31);
        }
        if (lane == 0) g_deg[g][r] = cnt < MAXD ? cnt : MAXD;
        return;
    }

    // ---------------- GEMM1: Wh = x @ Wcat, tile 128x64, + s1/s2 epilogue ----------
    __shared__ float As[16][132];
    __shared__ float Bs[16][64];
    int bx = bid & 31, by = bid >> 5;         // by in [0,8)
    int m0r = bx * 128, n0 = by * 64;
    int gsel = by >> 2, h = by & 3;
    const float* W  = gsel ? W2 : W1;         // [4,256,64]
    const float* av = (gsel ? a2 : a1) + h * 128;
    int tx = tid & 15, ty = tid >> 4;

    float acc[8][4] = {};
    for (int kb = 0; kb < FIN; kb += 16) {
        #pragma unroll
        for (int i = 0; i < 2; i++) {
            int e4 = i * 256 + tid;
            int m = e4 >> 2, k4 = e4 & 3;
            float4 v = *(const float4*)(x + (size_t)(m0r + m) * FIN + kb + k4 * 4);
            As[k4 * 4 + 0][m] = v.x; As[k4 * 4 + 1][m] = v.y;
            As[k4 * 4 + 2][m] = v.z; As[k4 * 4 + 3][m] = v.w;
        }
        {
            int k = tid >> 4, nf = (tid & 15) * 4;
            float4 bv = *(const float4*)(W + ((size_t)(h * FIN + kb + k)) * FHID + nf);
            *(float4*)&Bs[k][nf] = bv;
        }
        __syncthreads();
        #pragma unroll
        for (int kk = 0; kk < 16; kk++) {
            float a[8], b[4];
            #pragma unroll
            for (int r = 0; r < 8; r++) a[r] = As[kk][ty * 8 + r];
            #pragma unroll
            for (int c = 0; c < 4; c++) b[c] = Bs[kk][tx * 4 + c];
            #pragma unroll
            for (int r = 0; r < 8; r++)
                #pragma unroll
                for (int c = 0; c < 4; c++)
                    acc[r][c] += a[r] * b[c];
        }
        __syncthreads();
    }
    #pragma unroll
    for (int r = 0; r < 8; r++) {
        int m = m0r + ty * 8 + r;
        float4 v = make_float4(acc[r][0], acc[r][1], acc[r][2], acc[r][3]);
        *(float4*)&g_Wh[m][n0 + tx * 4] = v;
    }
    float a_s[4], a_d[4];
    #pragma unroll
    for (int c = 0; c < 4; c++) {
        a_s[c] = __ldg(av + tx * 4 + c);
        a_d[c] = __ldg(av + 64 + tx * 4 + c);
    }
    #pragma unroll
    for (int r = 0; r < 8; r++) {
        float s1 = 0.f, s2 = 0.f;
        #pragma unroll
        for (int c = 0; c < 4; c++) { s1 += acc[r][c] * a_s[c]; s2 += acc[r][c] * a_d[c]; }
        #pragma unroll
        for (int off = 1; off < 16; off <<= 1) {
            s1 += __shfl_xor_sync(0xffffffffu, s1, off);
            s2 += __shfl_xor_sync(0xffffffffu, s2, off);
        }
        if (tx == 0) {
            int m = m0r + ty * 8 + r;
            g_s1[gsel][h][m] = s1;
            g_s2[gsel][h][m] = s2;
        }
    }
}

// =====================================================================
// Layer-1 attention: one warp per (node, graph, head). Barrier-free.
// grid 4096 x 256 threads -> 8 warps/block = 1 node (2 g x 4 h).
// =====================================================================
__global__ void attn_layer1() {
    int tid  = threadIdx.x;
    int lane = tid & 31;
    int w    = tid >> 5;        // 0..7
    int h    = w & 3;
    int g    = w >> 2;
    int i    = blockIdx.x;

    int d = g_deg[g][i];
    // load cols + compute leaky(s1+s2) into registers (k = lane + 32*j)
    int   cr[4];
    float er[4];
    float s1v = g_s1[g][h][i];
    float m = -INFINITY;
    #pragma unroll
    for (int j = 0; j < 4; j++) {
        int k = lane + 32 * j;
        if (k < d) {
            int c = g_cols[g][i][k];
            cr[j] = c;
            float z = s1v + g_s2[g][h][c];
            z = z >= 0.f ? z : 0.2f * z;
            er[j] = z;
            m = fmaxf(m, z);
        } else { cr[j] = 0; er[j] = -INFINITY; }
    }
    #pragma unroll
    for (int off = 16; off; off >>= 1) m = fmaxf(m, __shfl_xor_sync(0xffffffffu, m, off));
    float sum = 0.f;
    #pragma unroll
    for (int j = 0; j < 4; j++) {
        int k = lane + 32 * j;
        float p = (k < d) ? __expf(er[j] - m) : 0.f;
        er[j] = p;
        sum += p;
    }
    #pragma unroll
    for (int off = 16; off; off >>= 1) sum += __shfl_xor_sync(0xffffffffu, sum, off);
    float inv = 1.f / sum;

    // gather: lane owns features (2*lane, 2*lane+1) of this head
    int colbase = g * 256 + h * 64 + 2 * lane;
    float ax = 0.f, ay = 0.f;
    for (int k = 0; k < d; k++) {
        int   c = __shfl_sync(0xffffffffu, cr[k >> 5], k & 31);
        float e = __shfl_sync(0xffffffffu, er[k >> 5], k & 31);
        float2 v = *(const float2*)&g_Wh[c][colbase];
        ax += e * v.x;
        ay += e * v.y;
    }
    ax *= inv; ay *= inv;
    float2 o;
    o.x = ax > 0.f ? ax : (__expf(ax) - 1.f);
    o.y = ay > 0.f ? ay : (__expf(ay) - 1.f);
    *(float2*)&g_hcat[g][i][h * 64 + 2 * lane] = o;
}

// =====================================================================
// GEMM2 (both graphs, one launch): Wh2_g = hcat_g @ Wo_g, tile 64x64,
// + s1o/s2o epilogue.  grid (64, 2), block 256, microtile 4x4.
// =====================================================================
__global__ void gemm2f(const float* __restrict__ Wo1, const float* __restrict__ Wo2,
                       const float* __restrict__ ao1, const float* __restrict__ ao2) {
    __shared__ float As[16][68];
    __shared__ float Bs[16][64];
    int g = blockIdx.y;
    int m0r = blockIdx.x * 64;
    const float* A  = &g_hcat[g][0][0];
    const float* B  = g ? Wo2 : Wo1;
    const float* ao = g ? ao2 : ao1;
    int tid = threadIdx.x;
    int tx = tid & 15, ty = tid >> 4;

    float acc[4][4] = {};
    for (int kb = 0; kb < 256; kb += 16) {
        {
            int m = tid >> 2, k4 = tid & 3;
            float4 v = *(const float4*)(A + (size_t)(m0r + m) * 256 + kb + k4 * 4);
            As[k4 * 4 + 0][m] = v.x; As[k4 * 4 + 1][m] = v.y;
            As[k4 * 4 + 2][m] = v.z; As[k4 * 4 + 3][m] = v.w;
        }
        {
            int k = tid >> 4, nf = (tid & 15) * 4;
            float4 bv = *(const float4*)(B + (size_t)(kb + k) * 64 + nf);
            *(float4*)&Bs[k][nf] = bv;
        }
        __syncthreads();
        #pragma unroll
        for (int kk = 0; kk < 16; kk++) {
            float a[4], b[4];
            #pragma unroll
            for (int r = 0; r < 4; r++) a[r] = As[kk][ty * 4 + r];
            #pragma unroll
            for (int c = 0; c < 4; c++) b[c] = Bs[kk][tx * 4 + c];
            #pragma unroll
            for (int r = 0; r < 4; r++)
                #pragma unroll
                for (int c = 0; c < 4; c++)
                    acc[r][c] += a[r] * b[c];
        }
        __syncthreads();
    }
    #pragma unroll
    for (int r = 0; r < 4; r++) {
        int m = m0r + ty * 4 + r;
        float4 v = make_float4(acc[r][0], acc[r][1], acc[r][2], acc[r][3]);
        *(float4*)&g_Wh2[g][m][tx * 4] = v;
    }
    float a_s[4], a_d[4];
    #pragma unroll
    for (int c = 0; c < 4; c++) {
        a_s[c] = __ldg(ao + tx * 4 + c);
        a_d[c] = __ldg(ao + 64 + tx * 4 + c);
    }
    #pragma unroll
    for (int r = 0; r < 4; r++) {
        float s1 = 0.f, s2 = 0.f;
        #pragma unroll
        for (int c = 0; c < 4; c++) { s1 += acc[r][c] * a_s[c]; s2 += acc[r][c] * a_d[c]; }
        #pragma unroll
        for (int off = 1; off < 16; off <<= 1) {
            s1 += __shfl_xor_sync(0xffffffffu, s1, off);
            s2 += __shfl_xor_sync(0xffffffffu, s2, off);
        }
        if (tx == 0) {
            int m = m0r + ty * 4 + r;
            g_s1o[g][m] = s1;
            g_s2o[g][m] = s2;
        }
    }
}

// =====================================================================
// Layer-2 attention + ELU + semantic fusion.
// One warp per (node, graph); 256-thread block handles 4 nodes.
// Only 2 barriers per block (fusion stage).
// =====================================================================
__global__ void attn2_final(const float* __restrict__ Wp1, const float* __restrict__ bp1,
                            const float* __restrict__ Wp2, float* __restrict__ out) {
    int tid  = threadIdx.x;
    int lane = tid & 31;
    int w    = tid >> 5;        // 0..7
    int n    = w >> 1;          // node slot 0..3
    int g    = w & 1;
    int i    = blockIdx.x * 4 + n;

    __shared__ float se[4][2][64];
    __shared__ float tt[4][2][16];

    int d = g_deg[g][i];
    int   cr[4];
    float er[4];
    float s1v = g_s1o[g][i];
    float m = -INFINITY;
    #pragma unroll
    for (int j = 0; j < 4; j++) {
        int k = lane + 32 * j;
        if (k < d) {
            int c = g_cols[g][i][k];
            cr[j] = c;
            float z = s1v + g_s2o[g][c];
            z = z >= 0.f ? z : 0.2f * z;
            er[j] = z;
            m = fmaxf(m, z);
        } else { cr[j] = 0; er[j] = -INFINITY; }
    }
    #pragma unroll
    for (int off = 16; off; off >>= 1) m = fmaxf(m, __shfl_xor_sync(0xffffffffu, m, off));
    float sum = 0.f;
    #pragma unroll
    for (int j = 0; j < 4; j++) {
        int k = lane + 32 * j;
        float p = (k < d) ? __expf(er[j] - m) : 0.f;
        er[j] = p;
        sum += p;
    }
    #pragma unroll
    for (int off = 16; off; off >>= 1) sum += __shfl_xor_sync(0xffffffffu, sum, off);
    float inv = 1.f / sum;

    float ax = 0.f, ay = 0.f;
    for (int k = 0; k < d; k++) {
        int   c = __shfl_sync(0xffffffffu, cr[k >> 5], k & 31);
        float e = __shfl_sync(0xffffffffu, er[k >> 5], k & 31);
        float2 v = *(const float2*)&g_Wh2[g][c][2 * lane];
        ax += e * v.x;
        ay += e * v.y;
    }
    ax *= inv; ay *= inv;
    se[n][g][2 * lane]     = ax > 0.f ? ax : (__expf(ax) - 1.f);
    se[n][g][2 * lane + 1] = ay > 0.f ? ay : (__expf(ay) - 1.f);
    __syncthreads();

    // projection: 128 threads = 4 nodes x 2 g x 16 p
    if (tid < 128) {
        int pn = tid >> 5, pg = (tid >> 4) & 1, p = tid & 15;
        float s = __ldg(bp1 + p);
        #pragma unroll
        for (int f = 0; f < 64; f++) s += se[pn][pg][f] * __ldg(Wp1 + f * NPROJ + p);
        tt[pn][pg][p] = tanhf(s);
    }
    __syncthreads();

    // output: 256 threads = 4 nodes x 64 feats; each recomputes beta (smem, cheap)
    int on = tid >> 6, f = tid & 63;
    float w0 = 0.f, w1 = 0.f;
    #pragma unroll
    for (int p = 0; p < NPROJ; p++) {
        float wp = __ldg(Wp2 + p);
        w0 += tt[on][0][p] * wp;
        w1 += tt[on][1][p] * wp;
    }
    float mm = fmaxf(w0, w1);
    float b0 = __expf(w0 - mm), b1 = __expf(w1 - mm);
    float ib = 1.f / (b0 + b1);
    int oi = blockIdx.x * 4 + on;
    out[(size_t)oi * 64 + f] = (b0 * se[on][0][f] + b1 * se[on][1][f]) * ib;
}

// ---------------- launch ----------------
extern "C" void kernel_launch(void* const* d_in, const int* in_sizes, int n_in,
                              void* d_out, int out_size) {
    const float* x    = (const float*)d_in[0];
    const float* sadj = (const float*)d_in[1];
    const float* sadj2= (const float*)d_in[2];
    const float* W1   = (const float*)d_in[3];
    const float* a1   = (const float*)d_in[4];
    const float* Wo1  = (const float*)d_in[5];
    const float* ao1  = (const float*)d_in[6];
    const float* W2   = (const float*)d_in[7];
    const float* a2   = (const float*)d_in[8];
    const float* Wo2  = (const float*)d_in[9];
    const float* ao2  = (const float*)d_in[10];
    const float* Wp1  = (const float*)d_in[11];
    const float* bp1  = (const float*)d_in[12];
    const float* Wp2  = (const float*)d_in[13];
    float* out = (float*)d_out;

    phase1<<<1280, 256>>>(x, W1, W2, a1, a2, sadj, sadj2);
    attn_layer1<<<4096, 256>>>();
    gemm2f<<<dim3(64, 2), 256>>>(Wo1, Wo2, ao1, ao2);
    attn2_final<<<1024, 256>>>(Wp1, bp1, Wp2, out);
}